// round 1
// baseline (speedup 1.0000x reference)
#include <cuda_runtime.h>
#include <cuda_bf16.h>
#include <float.h>
#include <stdint.h>

// Problem constants
#define BB 8
#define NN 4096
#define SS 1024
#define KK 32
#define R_TOTAL (BB*SS*KK)            // 262144 rows through the MLP
#define INV_R   (1.0f/262144.0f)
#define BN_EPS  1e-5f

// ---------------- scratch (static device globals; no allocation) -------------
__device__ int   g_idx[R_TOTAL];                       // 1 MB
__device__ float g_y0[(size_t)R_TOTAL*64];             // 64 MB  pre-BN layer0
__device__ float g_y1[(size_t)R_TOTAL*64];             // 64 MB  pre-BN layer1
__device__ float g_y2[(size_t)R_TOTAL*128];            // 128 MB pre-BN layer2
__device__ float g_sum[128];                           // per-channel sums (zeroed by finalize)
__device__ float g_sqsum[128];
__device__ float g_scale[128];                         // folded BN affine: y*scale+bias
__device__ float g_bias[128];

// =============================================================================
// KNN: one warp per query. Each lane holds one of the 32 best slots in a
// register; insertion via ballot + warp argmax. Order of results irrelevant
// (downstream is permutation invariant).
// =============================================================================
__global__ void knn_kernel(const float* __restrict__ xyz, float* __restrict__ out_xyz)
{
    __shared__ float sx[2048], sy[2048], sz[2048], sn[2048];
    const unsigned FULL = 0xffffffffu;
    int tid  = threadIdx.x;
    int warp = tid >> 5, lane = tid & 31;
    int b     = blockIdx.x >> 6;               // 64 blocks per batch
    int sBase = (blockIdx.x & 63) * 16;
    int s     = sBase + warp;                  // query index in [0,1024)

    const float* xb = xyz + (size_t)b * NN * 3;
    float qx = xb[(4*s)*3+0];
    float qy = xb[(4*s)*3+1];
    float qz = xb[(4*s)*3+2];
    float qn = qx*qx + qy*qy + qz*qz;

    float bd = FLT_MAX;  int bi = 0;           // this lane's slot
    float bound = FLT_MAX;                     // max over the 32 slots

    for (int tb = 0; tb < NN; tb += 2048) {
        __syncthreads();
        for (int i = tid; i < 2048; i += 512) {
            int n = tb + i;
            float px = xb[n*3+0], py = xb[n*3+1], pz = xb[n*3+2];
            sx[i] = px; sy[i] = py; sz[i] = pz;
            sn[i] = px*px + py*py + pz*pz;
        }
        __syncthreads();

        for (int it = 0; it < 64; it++) {
            int j = it*32 + lane;
            // same formula as reference: |q|^2 + |p|^2 - 2 q.p
            float d = qn + sn[j] - 2.0f*(qx*sx[j] + qy*sy[j] + qz*sz[j]);
            int   n = tb + j;
            bool pend = (d < bound);
            unsigned m;
            while ((m = __ballot_sync(FULL, pend)) != 0) {
                int src  = __ffs(m) - 1;
                float dI = __shfl_sync(FULL, d, src);
                int   iI = __shfl_sync(FULL, n, src);
                // warp argmax over slot values (all lanes converge on same (v,l))
                float v = bd; int l = lane;
                #pragma unroll
                for (int off = 16; off; off >>= 1) {
                    float v2 = __shfl_xor_sync(FULL, v, off);
                    int   l2 = __shfl_xor_sync(FULL, l, off);
                    if (v2 > v || (v2 == v && l2 > l)) { v = v2; l = l2; }
                }
                if (lane == l) { bd = dI; bi = iI; }
                // new bound = max over slots
                float nb = bd;
                #pragma unroll
                for (int off = 16; off; off >>= 1)
                    nb = fmaxf(nb, __shfl_xor_sync(FULL, nb, off));
                bound = nb;
                if (lane == src) pend = false;
                pend = pend && (d < bound);
            }
        }
    }

    int qg = b*SS + s;
    g_idx[qg*32 + lane] = bi;
    if (lane == 0) {
        out_xyz[qg*3+0] = qx;
        out_xyz[qg*3+1] = qy;
        out_xyz[qg*3+2] = qz;
    }
}

// =============================================================================
// Layer0: gather features (xyz[idx]-q | points[idx]) and 9->64 matmul.
// Writes pre-BN y0 and accumulates per-channel sum/sumsq.
// Block: 256 threads = 64 channels x 4 row-lanes, 64 rows per block.
// =============================================================================
__global__ void l0_kernel(const float* __restrict__ xyz,
                          const float* __restrict__ points,
                          const float* __restrict__ W0)
{
    __shared__ float sW[64*9];
    __shared__ float sS1[64], sS2[64];
    int tid = threadIdx.x;
    for (int i = tid; i < 576; i += 256) sW[i] = W0[i];
    if (tid < 64) { sS1[tid] = 0.f; sS2[tid] = 0.f; }
    __syncthreads();

    int c  = tid & 63;
    int rl = tid >> 6;
    int rowBase = blockIdx.x * 64;
    float s1 = 0.f, s2 = 0.f;

    for (int it = 0; it < 16; it++) {
        int row = rowBase + it*4 + rl;
        int b = row >> 15;
        int s = (row >> 5) & 1023;
        int n = g_idx[row];
        const float* xb = xyz    + (size_t)b*NN*3;
        const float* pb = points + (size_t)b*NN*6 + (size_t)n*6;
        float x0 = xb[n*3+0] - xb[(4*s)*3+0];
        float x1 = xb[n*3+1] - xb[(4*s)*3+1];
        float x2 = xb[n*3+2] - xb[(4*s)*3+2];
        const float* w = &sW[c*9];
        float acc = w[0]*x0 + w[1]*x1 + w[2]*x2
                  + w[3]*pb[0] + w[4]*pb[1] + w[5]*pb[2]
                  + w[6]*pb[3] + w[7]*pb[4] + w[8]*pb[5];
        g_y0[(size_t)row*64 + c] = acc;
        s1 += acc; s2 += acc*acc;
    }
    atomicAdd(&sS1[c], s1);
    atomicAdd(&sS2[c], s2);
    __syncthreads();
    if (tid < 64) {
        atomicAdd(&g_sum[tid],   sS1[tid]);
        atomicAdd(&g_sqsum[tid], sS2[tid]);
    }
}

// =============================================================================
// finalize: turn accumulated sums into folded BN affine, re-zero accumulators
// (keeps the graph replayable).
// =============================================================================
__global__ void finalize_kernel(const float* __restrict__ gamma,
                                const float* __restrict__ beta, int C)
{
    int c = threadIdx.x;
    if (c < C) {
        float m  = g_sum[c]   * INV_R;
        float v  = g_sqsum[c] * INV_R - m*m;
        float sc = gamma[c] * rsqrtf(v + BN_EPS);
        g_scale[c] = sc;
        g_bias[c]  = beta[c] - m*sc;
        g_sum[c]   = 0.f;
        g_sqsum[c] = 0.f;
    }
}

// =============================================================================
// GEMM layers 1/2: z = relu(yin*scale+bias) (64 in-ch), yout = z @ W^T.
// Tile: 64 rows x 64 out-ch per block, thread computes 4x4.
// sWt stored k-major -> conflict-free float4 w-loads; z loads are broadcasts.
// Accumulates per-channel stats of yout.
// L==1: g_y0 -> g_y1 (OUT=64);  L==2: g_y1 -> g_y2 (OUT=128, gridDim.y=2)
// =============================================================================
template<int L, int OUT>
__global__ void gemm_kernel(const float* __restrict__ W)
{
    __shared__ float sZ [64][68];
    __shared__ float sWt[64][68];
    __shared__ float sS1[64], sS2[64];

    const float* yin  = (L == 1) ? g_y0 : g_y1;
    float*       yout = (L == 1) ? g_y1 : g_y2;

    int tid     = threadIdx.x;
    int rowBase = blockIdx.x * 64;
    int cTile   = blockIdx.y * 64;

    // stage z = relu(BN(yin)) ; thread -> (k-quad, row), coalesced global reads
    {
        int k4 = (tid & 15) * 4;
        float a0 = g_scale[k4+0], d0 = g_bias[k4+0];
        float a1 = g_scale[k4+1], d1 = g_bias[k4+1];
        float a2 = g_scale[k4+2], d2 = g_bias[k4+2];
        float a3 = g_scale[k4+3], d3 = g_bias[k4+3];
        for (int rr = (tid >> 4); rr < 64; rr += 16) {
            float4 v = *(const float4*)&yin[(size_t)(rowBase+rr)*64 + k4];
            v.x = fmaxf(fmaf(v.x, a0, d0), 0.f);
            v.y = fmaxf(fmaf(v.y, a1, d1), 0.f);
            v.z = fmaxf(fmaf(v.z, a2, d2), 0.f);
            v.w = fmaxf(fmaf(v.w, a3, d3), 0.f);
            *(float4*)&sZ[rr][k4] = v;
        }
    }
    // stage W tile k-major: lanes -> distinct c (conflict-free STS)
    {
        int k4 = (tid >> 4) * 4;
        for (int cc = (tid & 15); cc < 64; cc += 16) {
            float4 w = *(const float4*)&W[(size_t)(cTile+cc)*64 + k4];
            sWt[k4+0][cc] = w.x;
            sWt[k4+1][cc] = w.y;
            sWt[k4+2][cc] = w.z;
            sWt[k4+3][cc] = w.w;
        }
    }
    if (tid < 64) { sS1[tid] = 0.f; sS2[tid] = 0.f; }
    __syncthreads();

    int tx = tid & 15, ty = tid >> 4;
    int c0 = tx*4,     r0 = ty*4;
    float acc[4][4] = {};

    #pragma unroll 4
    for (int k = 0; k < 64; k += 4) {
        float4 w0 = *(const float4*)&sWt[k+0][c0];
        float4 w1 = *(const float4*)&sWt[k+1][c0];
        float4 w2 = *(const float4*)&sWt[k+2][c0];
        float4 w3 = *(const float4*)&sWt[k+3][c0];
        #pragma unroll
        for (int i = 0; i < 4; i++) {
            float4 z = *(const float4*)&sZ[r0+i][k];
            acc[i][0] = fmaf(z.x,w0.x, fmaf(z.y,w1.x, fmaf(z.z,w2.x, fmaf(z.w,w3.x, acc[i][0]))));
            acc[i][1] = fmaf(z.x,w0.y, fmaf(z.y,w1.y, fmaf(z.z,w2.y, fmaf(z.w,w3.y, acc[i][1]))));
            acc[i][2] = fmaf(z.x,w0.z, fmaf(z.y,w1.z, fmaf(z.z,w2.z, fmaf(z.w,w3.z, acc[i][2]))));
            acc[i][3] = fmaf(z.x,w0.w, fmaf(z.y,w1.w, fmaf(z.z,w2.w, fmaf(z.w,w3.w, acc[i][3]))));
        }
    }

    // write pre-BN outputs + stats
    #pragma unroll
    for (int i = 0; i < 4; i++) {
        float4 o = make_float4(acc[i][0], acc[i][1], acc[i][2], acc[i][3]);
        *(float4*)&yout[(size_t)(rowBase + r0 + i)*OUT + cTile + c0] = o;
    }
    #pragma unroll
    for (int j = 0; j < 4; j++) {
        float s1 = acc[0][j] + acc[1][j] + acc[2][j] + acc[3][j];
        float s2 = acc[0][j]*acc[0][j] + acc[1][j]*acc[1][j]
                 + acc[2][j]*acc[2][j] + acc[3][j]*acc[3][j];
        atomicAdd(&sS1[c0+j], s1);
        atomicAdd(&sS2[c0+j], s2);
    }
    __syncthreads();
    if (tid < 64) {
        atomicAdd(&g_sum[cTile + tid],   sS1[tid]);
        atomicAdd(&g_sqsum[cTile + tid], sS2[tid]);
    }
}

// =============================================================================
// Final: BN+relu on y2, max over the 32 neighbors, write new_points.
// One block per (b,s) group; thread = channel.
// =============================================================================
__global__ void max_kernel(float* __restrict__ out_pts)
{
    int g = blockIdx.x;          // 8192 groups
    int c = threadIdx.x;         // 128 channels
    float sc = g_scale[c], bi = g_bias[c];
    const float* base = g_y2 + (size_t)g*KK*128 + c;
    float m = 0.f;               // relu output is >= 0
    #pragma unroll 8
    for (int k = 0; k < KK; k++) {
        float y = base[(size_t)k*128];
        m = fmaxf(m, fmaf(y, sc, bi));
    }
    out_pts[(size_t)g*128 + c] = m;
}

// =============================================================================
extern "C" void kernel_launch(void* const* d_in, const int* in_sizes, int n_in,
                              void* d_out, int out_size)
{
    const float* xyz    = (const float*)d_in[0];
    const float* points = (const float*)d_in[1];
    const float* W0     = (const float*)d_in[2];
    const float* g0     = (const float*)d_in[3];
    const float* b0     = (const float*)d_in[4];
    const float* W1     = (const float*)d_in[5];
    const float* g1     = (const float*)d_in[6];
    const float* b1     = (const float*)d_in[7];
    const float* W2     = (const float*)d_in[8];
    const float* g2     = (const float*)d_in[9];
    const float* b2     = (const float*)d_in[10];

    float* out      = (float*)d_out;
    float* out_xyz  = out;                       // 8*1024*3
    float* out_pts  = out + (size_t)BB*SS*3;     // 8*1024*128

    knn_kernel<<<512, 512>>>(xyz, out_xyz);
    l0_kernel<<<R_TOTAL/64, 256>>>(xyz, points, W0);
    finalize_kernel<<<1, 128>>>(g0, b0, 64);
    gemm_kernel<1, 64><<<dim3(R_TOTAL/64, 1), 256>>>(W1);
    finalize_kernel<<<1, 128>>>(g1, b1, 64);
    gemm_kernel<2, 128><<<dim3(R_TOTAL/64, 2), 256>>>(W2);
    finalize_kernel<<<1, 128>>>(g2, b2, 128);
    max_kernel<<<BB*SS, 128>>>(out_pts);
}

// round 2
// speedup vs baseline: 1.0783x; 1.0783x over previous
#include <cuda_runtime.h>
#include <cuda_bf16.h>
#include <float.h>
#include <stdint.h>

// Problem constants
#define BB 8
#define NN 4096
#define SS 1024
#define KK 32
#define R_TOTAL (BB*SS*KK)            // 262144 rows through the MLP
#define INV_R   (1.0f/262144.0f)
#define BN_EPS  1e-5f

// ---------------- scratch (static device globals; no allocation) -------------
__device__ int   g_idx[R_TOTAL];                       // 1 MB
__device__ float g_y0[(size_t)R_TOTAL*64];             // 64 MB  pre-BN layer0
__device__ float g_y1[(size_t)R_TOTAL*64];             // 64 MB  pre-BN layer1
__device__ float g_gmax[(size_t)BB*SS*128];            // 4 MB per-group pre-BN max (layer2)
__device__ float g_gmin[(size_t)BB*SS*128];            // 4 MB per-group pre-BN min
__device__ float g_sum[128];                           // per-channel sums (zeroed by finalize)
__device__ float g_sqsum[128];
__device__ float g_scale[128];                         // folded BN affine: y*scale+bias
__device__ float g_bias[128];

// =============================================================================
// KNN: one warp per query. Each lane holds one of the 32 best slots in a
// register; insertion via ballot + warp argmax. Order of results irrelevant
// (downstream is permutation invariant).
// =============================================================================
__global__ void knn_kernel(const float* __restrict__ xyz, float* __restrict__ out_xyz)
{
    __shared__ float sx[2048], sy[2048], sz[2048], sn[2048];
    const unsigned FULL = 0xffffffffu;
    int tid  = threadIdx.x;
    int warp = tid >> 5, lane = tid & 31;
    int b     = blockIdx.x >> 6;               // 64 blocks per batch
    int sBase = (blockIdx.x & 63) * 16;
    int s     = sBase + warp;                  // query index in [0,1024)

    const float* xb = xyz + (size_t)b * NN * 3;
    float qx = xb[(4*s)*3+0];
    float qy = xb[(4*s)*3+1];
    float qz = xb[(4*s)*3+2];
    float qn = qx*qx + qy*qy + qz*qz;

    float bd = FLT_MAX;  int bi = 0;           // this lane's slot
    float bound = FLT_MAX;                     // max over the 32 slots

    for (int tb = 0; tb < NN; tb += 2048) {
        __syncthreads();
        for (int i = tid; i < 2048; i += 512) {
            int n = tb + i;
            float px = xb[n*3+0], py = xb[n*3+1], pz = xb[n*3+2];
            sx[i] = px; sy[i] = py; sz[i] = pz;
            sn[i] = px*px + py*py + pz*pz;
        }
        __syncthreads();

        for (int it = 0; it < 64; it++) {
            int j = it*32 + lane;
            // same formula as reference: |q|^2 + |p|^2 - 2 q.p
            float d = qn + sn[j] - 2.0f*(qx*sx[j] + qy*sy[j] + qz*sz[j]);
            int   n = tb + j;
            bool pend = (d < bound);
            unsigned m;
            while ((m = __ballot_sync(FULL, pend)) != 0) {
                int src  = __ffs(m) - 1;
                float dI = __shfl_sync(FULL, d, src);
                int   iI = __shfl_sync(FULL, n, src);
                // warp argmax over slot values (all lanes converge on same (v,l))
                float v = bd; int l = lane;
                #pragma unroll
                for (int off = 16; off; off >>= 1) {
                    float v2 = __shfl_xor_sync(FULL, v, off);
                    int   l2 = __shfl_xor_sync(FULL, l, off);
                    if (v2 > v || (v2 == v && l2 > l)) { v = v2; l = l2; }
                }
                if (lane == l) { bd = dI; bi = iI; }
                // new bound = max over slots
                float nb = bd;
                #pragma unroll
                for (int off = 16; off; off >>= 1)
                    nb = fmaxf(nb, __shfl_xor_sync(FULL, nb, off));
                bound = nb;
                if (lane == src) pend = false;
                pend = pend && (d < bound);
            }
        }
    }

    int qg = b*SS + s;
    g_idx[qg*32 + lane] = bi;
    if (lane == 0) {
        out_xyz[qg*3+0] = qx;
        out_xyz[qg*3+1] = qy;
        out_xyz[qg*3+2] = qz;
    }
}

// =============================================================================
// Layer0: gather features (xyz[idx]-q | points[idx]) and 9->64 matmul.
// Writes pre-BN y0 and accumulates per-channel sum/sumsq.
// =============================================================================
__global__ void l0_kernel(const float* __restrict__ xyz,
                          const float* __restrict__ points,
                          const float* __restrict__ W0)
{
    __shared__ float sW[64*9];
    __shared__ float sS1[64], sS2[64];
    int tid = threadIdx.x;
    for (int i = tid; i < 576; i += 256) sW[i] = W0[i];
    if (tid < 64) { sS1[tid] = 0.f; sS2[tid] = 0.f; }
    __syncthreads();

    int c  = tid & 63;
    int rl = tid >> 6;
    int rowBase = blockIdx.x * 64;
    float s1 = 0.f, s2 = 0.f;

    for (int it = 0; it < 16; it++) {
        int row = rowBase + it*4 + rl;
        int b = row >> 15;
        int s = (row >> 5) & 1023;
        int n = g_idx[row];
        const float* xb = xyz    + (size_t)b*NN*3;
        const float* pb = points + (size_t)b*NN*6 + (size_t)n*6;
        float x0 = xb[n*3+0] - xb[(4*s)*3+0];
        float x1 = xb[n*3+1] - xb[(4*s)*3+1];
        float x2 = xb[n*3+2] - xb[(4*s)*3+2];
        const float* w = &sW[c*9];
        float acc = w[0]*x0 + w[1]*x1 + w[2]*x2
                  + w[3]*pb[0] + w[4]*pb[1] + w[5]*pb[2]
                  + w[6]*pb[3] + w[7]*pb[4] + w[8]*pb[5];
        g_y0[(size_t)row*64 + c] = acc;
        s1 += acc; s2 += acc*acc;
    }
    atomicAdd(&sS1[c], s1);
    atomicAdd(&sS2[c], s2);
    __syncthreads();
    if (tid < 64) {
        atomicAdd(&g_sum[tid],   sS1[tid]);
        atomicAdd(&g_sqsum[tid], sS2[tid]);
    }
}

// =============================================================================
// finalize: accumulated sums -> folded BN affine; re-zero accumulators.
// =============================================================================
__global__ void finalize_kernel(const float* __restrict__ gamma,
                                const float* __restrict__ beta, int C)
{
    int c = threadIdx.x;
    if (c < C) {
        float m  = g_sum[c]   * INV_R;
        float v  = g_sqsum[c] * INV_R - m*m;
        float sc = gamma[c] * rsqrtf(v + BN_EPS);
        g_scale[c] = sc;
        g_bias[c]  = beta[c] - m*sc;
        g_sum[c]   = 0.f;
        g_sqsum[c] = 0.f;
    }
}

// =============================================================================
// GEMM layers 1/2, 8x8 per-thread tiles.
//   L==1: z=relu(BN(y0)); y1 = z @ W1^T. Tile 256 rows x 64 cols, 256 thr.
//   L==2: z=relu(BN(y1)); y2 = z @ W2^T. Tile 128 rows x 128 cols, 256 thr.
//         y2 NOT stored: per-group (32 consecutive rows) pre-BN max/min
//         reduced in-block and written to g_gmax/g_gmin (8 MB vs 128 MB).
// Per k-step: 8 broadcast scalar z LDS + 2 LDS.128 w vs 64 FMA -> fma-bound.
// =============================================================================
template<int L>
__global__ void __launch_bounds__(256) gemm_kernel(const float* __restrict__ W)
{
    constexpr int ROWS = (L == 1) ? 256 : 128;
    constexpr int COLS = (L == 1) ? 64  : 128;
    constexpr int PZ   = 68;          // sZ row pitch
    constexpr int PW   = COLS + 8;    // sWt row pitch (72 / 136)
    constexpr int TXC  = COLS / 8;    // col-thread groups (8 / 16)

    extern __shared__ float sm[];
    float* sZ  = sm;                  // [ROWS][PZ]
    float* sWt = sm + ROWS * PZ;      // [64][PW]   (k-major)
    __shared__ float sS1[COLS], sS2[COLS];

    const float* yin = (L == 1) ? g_y0 : g_y1;

    int tid     = threadIdx.x;
    int rowBase = blockIdx.x * ROWS;

    // stage z = relu(BN(yin)); coalesced float4 global reads
    {
        int k4 = (tid & 15) * 4;
        float a0 = g_scale[k4+0], d0 = g_bias[k4+0];
        float a1 = g_scale[k4+1], d1 = g_bias[k4+1];
        float a2 = g_scale[k4+2], d2 = g_bias[k4+2];
        float a3 = g_scale[k4+3], d3 = g_bias[k4+3];
        for (int rr = (tid >> 4); rr < ROWS; rr += 16) {
            float4 v = *(const float4*)&yin[(size_t)(rowBase + rr)*64 + k4];
            v.x = fmaxf(fmaf(v.x, a0, d0), 0.f);
            v.y = fmaxf(fmaf(v.y, a1, d1), 0.f);
            v.z = fmaxf(fmaf(v.z, a2, d2), 0.f);
            v.w = fmaxf(fmaf(v.w, a3, d3), 0.f);
            *(float4*)&sZ[rr*PZ + k4] = v;
        }
    }
    // stage W k-major
    {
        int k4 = (tid >> 4) * 4;
        for (int cc = (tid & 15); cc < COLS; cc += 16) {
            float4 w = *(const float4*)&W[(size_t)cc*64 + k4];
            sWt[(k4+0)*PW + cc] = w.x;
            sWt[(k4+1)*PW + cc] = w.y;
            sWt[(k4+2)*PW + cc] = w.z;
            sWt[(k4+3)*PW + cc] = w.w;
        }
    }
    if (tid < COLS) { sS1[tid] = 0.f; sS2[tid] = 0.f; }
    __syncthreads();

    int tx = tid % TXC, ty = tid / TXC;
    int c0 = tx * 8,    r0 = ty * 8;
    float acc[8][8] = {};

    #pragma unroll 4
    for (int k = 0; k < 64; k++) {
        float wr[8], zr[8];
        *(float4*)&wr[0] = *(const float4*)&sWt[k*PW + c0];
        *(float4*)&wr[4] = *(const float4*)&sWt[k*PW + c0 + 4];
        #pragma unroll
        for (int i = 0; i < 8; i++) zr[i] = sZ[(r0+i)*PZ + k];
        #pragma unroll
        for (int i = 0; i < 8; i++)
            #pragma unroll
            for (int j = 0; j < 8; j++)
                acc[i][j] = fmaf(zr[i], wr[j], acc[i][j]);
    }

    // per-channel stats
    #pragma unroll
    for (int j = 0; j < 8; j++) {
        float s1 = 0.f, s2 = 0.f;
        #pragma unroll
        for (int i = 0; i < 8; i++) { s1 += acc[i][j]; s2 += acc[i][j]*acc[i][j]; }
        atomicAdd(&sS1[c0+j], s1);
        atomicAdd(&sS2[c0+j], s2);
    }

    if (L == 1) {
        // write full pre-BN activations (consumed by layer2)
        #pragma unroll
        for (int i = 0; i < 8; i++) {
            float4 o0 = make_float4(acc[i][0], acc[i][1], acc[i][2], acc[i][3]);
            float4 o1 = make_float4(acc[i][4], acc[i][5], acc[i][6], acc[i][7]);
            float* dst = &g_y1[(size_t)(rowBase + r0 + i)*64 + c0];
            *(float4*)&dst[0] = o0;
            *(float4*)&dst[4] = o1;
        }
    } else {
        // per-group pre-BN max/min reduction.
        // rows in this block: 128 = 4 complete groups of 32 (rows are (b,s,k)-ordered).
        // thread's 8 rows lie inside group (ty>>2).
        __syncthreads();               // done reading sZ; reuse it
        float* pMax = sZ;              // [16][PW]
        float* pMin = sZ + 16*PW;      // [16][PW]
        #pragma unroll
        for (int j = 0; j < 8; j++) {
            float mx = acc[0][j], mn = acc[0][j];
            #pragma unroll
            for (int i = 1; i < 8; i++) { mx = fmaxf(mx, acc[i][j]); mn = fminf(mn, acc[i][j]); }
            pMax[ty*PW + c0 + j] = mx;
            pMin[ty*PW + c0 + j] = mn;
        }
        __syncthreads();
        for (int e = tid; e < 4*128; e += 256) {
            int g = e >> 7, c = e & 127;
            float mx = fmaxf(fmaxf(pMax[(4*g+0)*PW + c], pMax[(4*g+1)*PW + c]),
                             fmaxf(pMax[(4*g+2)*PW + c], pMax[(4*g+3)*PW + c]));
            float mn = fminf(fminf(pMin[(4*g+0)*PW + c], pMin[(4*g+1)*PW + c]),
                             fminf(pMin[(4*g+2)*PW + c], pMin[(4*g+3)*PW + c]));
            size_t go = (size_t)(blockIdx.x*4 + g)*128 + c;
            g_gmax[go] = mx;
            g_gmin[go] = mn;
        }
    }

    __syncthreads();
    if (tid < COLS) {
        atomicAdd(&g_sum[tid],   sS1[tid]);
        atomicAdd(&g_sqsum[tid], sS2[tid]);
    }
}

// =============================================================================
// Final: apply layer2 BN affine + relu to the per-group max/min:
//   max_k relu(y*sc+bi) = relu( (sc>=0 ? ymax : ymin)*sc + bi )
// =============================================================================
__global__ void final_kernel(float* __restrict__ out_pts)
{
    int i = blockIdx.x * 256 + threadIdx.x;    // over 8192*128
    int c = i & 127;
    float sc = g_scale[c], bi = g_bias[c];
    float y  = (sc >= 0.f) ? g_gmax[i] : g_gmin[i];
    out_pts[i] = fmaxf(fmaf(y, sc, bi), 0.f);
}

// =============================================================================
extern "C" void kernel_launch(void* const* d_in, const int* in_sizes, int n_in,
                              void* d_out, int out_size)
{
    const float* xyz    = (const float*)d_in[0];
    const float* points = (const float*)d_in[1];
    const float* W0     = (const float*)d_in[2];
    const float* g0     = (const float*)d_in[3];
    const float* b0     = (const float*)d_in[4];
    const float* W1     = (const float*)d_in[5];
    const float* g1     = (const float*)d_in[6];
    const float* b1     = (const float*)d_in[7];
    const float* W2     = (const float*)d_in[8];
    const float* g2     = (const float*)d_in[9];
    const float* b2     = (const float*)d_in[10];

    float* out      = (float*)d_out;
    float* out_xyz  = out;                       // 8*1024*3
    float* out_pts  = out + (size_t)BB*SS*3;     // 8*1024*128

    const size_t smem1 = (size_t)(256*68 + 64*72)  * sizeof(float);  // 88064
    const size_t smem2 = (size_t)(128*68 + 64*136) * sizeof(float);  // 69632
    cudaFuncSetAttribute(gemm_kernel<1>, cudaFuncAttributeMaxDynamicSharedMemorySize, (int)smem1);
    cudaFuncSetAttribute(gemm_kernel<2>, cudaFuncAttributeMaxDynamicSharedMemorySize, (int)smem2);

    knn_kernel<<<512, 512>>>(xyz, out_xyz);
    l0_kernel<<<R_TOTAL/64, 256>>>(xyz, points, W0);
    finalize_kernel<<<1, 128>>>(g0, b0, 64);
    gemm_kernel<1><<<R_TOTAL/256, 256, smem1>>>(W1);
    finalize_kernel<<<1, 128>>>(g1, b1, 64);
    gemm_kernel<2><<<R_TOTAL/128, 256, smem2>>>(W2);
    finalize_kernel<<<1, 128>>>(g2, b2, 128);
    final_kernel<<<(BB*SS*128)/256, 256>>>(out_pts);
}